// round 7
// baseline (speedup 1.0000x reference)
#include <cuda_runtime.h>
#include <cuda_bf16.h>
#include <cstdint>

// ---------------- problem constants ----------------
#define NN 131072
#define EE 524288
#define DD 100
#define DA 50
#define DC 30
#define ND (NN*DD)          // 13,107,200

// ---------------- scratch (static device globals; no allocation) ----------------
__device__ float g_h[ND];
__device__ float g_fm[ND];
__device__ float g_msg[ND];
// B images for GRU mma GEMMs: 2 dirs x [ih_r, ih_z, ih_n, hh_r, hh_z, hh_n],
// each [104 n][312 k] bf16 row-major (only 304 k used; 104x156 u32 = 64896 B)
__device__ unsigned char g_Bimg[12][64896];

// CSR scratch (edges constant -> build once per launch)
__device__ int g_degF[NN], g_degB[NN];
__device__ int g_rpF[NN], g_rpB[NN];
__device__ int g_fillF[NN], g_fillB[NN];
__device__ int g_eF[EE], g_eB[EE];
__device__ int g_bsum[256];

// ---------------- f32x2 packed-FMA helpers (MLP path) ----------------
typedef unsigned long long u64;

__device__ __forceinline__ u64 ffma2(u64 a, u64 b, u64 c) {
    u64 d;
    asm("fma.rn.f32x2 %0, %1, %2, %3;" : "=l"(d) : "l"(a), "l"(b), "l"(c));
    return d;
}
__device__ __forceinline__ u64 dup2(float x) {
    u64 d;
    asm("mov.b64 %0, {%1, %1};" : "=l"(d) : "f"(x));
    return d;
}
__device__ __forceinline__ u64 pk2(float a, float b) {
    u64 d;
    asm("mov.b64 %0, {%1, %2};" : "=l"(d) : "f"(a), "f"(b));
    return d;
}
__device__ __forceinline__ float2 unpk(u64 a) {
    float2 r;
    asm("mov.b64 {%0, %1}, %2;" : "=f"(r.x), "=f"(r.y) : "l"(a));
    return r;
}
__device__ __forceinline__ float sigf(float v) {
    return 1.0f / (1.0f + __expf(-v));
}

// ---------------- mma.sync helpers ----------------
__device__ __forceinline__ uint32_t smem_u32(const void* p) {
    uint32_t a;
    asm("{ .reg .u64 t; cvta.to.shared.u64 t, %1; cvt.u32.u64 %0, t; }" : "=r"(a) : "l"(p));
    return a;
}
#define LDSM4(r0, r1, r2, r3, addr) \
    asm volatile("ldmatrix.sync.aligned.m8n8.x4.shared.b16 {%0,%1,%2,%3}, [%4];" \
        : "=r"(r0), "=r"(r1), "=r"(r2), "=r"(r3) : "r"(addr))
#define LDSM2(r0, r1, addr) \
    asm volatile("ldmatrix.sync.aligned.m8n8.x2.shared.b16 {%0,%1}, [%2];" \
        : "=r"(r0), "=r"(r1) : "r"(addr))
#define MMA16816(c, a0, a1, a2, a3, b0, b1) \
    asm volatile("mma.sync.aligned.m16n8k16.row.col.f32.bf16.bf16.f32 " \
        "{%0,%1,%2,%3}, {%4,%5,%6,%7}, {%8,%9}, {%0,%1,%2,%3};" \
        : "+f"((c)[0]), "+f"((c)[1]), "+f"((c)[2]), "+f"((c)[3]) \
        : "r"(a0), "r"(a1), "r"(a2), "r"(a3), "r"(b0), "r"(b1))

// ---------------- init: h = features @ init_W + init_b ----------------
__global__ void init_kernel(const float* __restrict__ feat,
                            const float* __restrict__ W,
                            const float* __restrict__ b) {
    int i = blockIdx.x * blockDim.x + threadIdx.x;
    if (i >= ND) return;
    int n = i / DD;
    int d = i - n * DD;
    float f0 = feat[n * 4 + 0], f1 = feat[n * 4 + 1];
    float f2 = feat[n * 4 + 2], f3 = feat[n * 4 + 3];
    g_h[i] = b[d] + f0 * W[d] + f1 * W[DD + d] + f2 * W[2 * DD + d] + f3 * W[3 * DD + d];
}

// ---------------- one-time B-image build (split-bf16, [n][k] row-major) ----------------
// K layout (304 used of 312): [hi_W(0..99), lo_W(0..99), hi_W(0..99), 0...]
// matching A layout:          [hi_x,        hi_x,        lo_x,        0...]
__global__ void prep_b_kernel(const float* __restrict__ fWih, const float* __restrict__ fWhh,
                              const float* __restrict__ bWih, const float* __restrict__ bWhh) {
    int t = blockIdx.x * blockDim.x + threadIdx.x;   // 12 * 104 * 156
    if (t >= 12 * 16224) return;
    int img = t / 16224;
    int rem = t - img * 16224;
    int n = rem / 156;
    int kp = rem - n * 156;
    int k = kp * 2;
    int dir = img / 6;
    int cat = img % 6;          // 0..2 = ih (r,z,n), 3..5 = hh (r,z,n)
    const float* W = (dir == 0) ? ((cat < 3) ? fWih : fWhh)
                                : ((cat < 3) ? bWih : bWhh);
    int gate = cat % 3;
    unsigned out = 0;
    if (n < 100 && k < 300) {
        int seg = k / 100;
        int d0 = k - seg * 100;
        float w0 = W[(gate * 100 + n) * 100 + d0];
        float w1 = W[(gate * 100 + n) * 100 + d0 + 1];
        __nv_bfloat16 h0 = __float2bfloat16(w0), h1 = __float2bfloat16(w1);
        unsigned short u0, u1;
        if (seg == 1) {   // lo segment
            __nv_bfloat16 l0 = __float2bfloat16(w0 - __bfloat162float(h0));
            __nv_bfloat16 l1 = __float2bfloat16(w1 - __bfloat162float(h1));
            u0 = *(unsigned short*)&l0; u1 = *(unsigned short*)&l1;
        } else {
            u0 = *(unsigned short*)&h0; u1 = *(unsigned short*)&h1;
        }
        out = (unsigned)u0 | ((unsigned)u1 << 16);
    }
    ((unsigned*)g_Bimg[img])[n * 156 + kp] = out;
}

// ---------------- CSR build kernels ----------------
__global__ void zero_deg_kernel() {
    int i = blockIdx.x * blockDim.x + threadIdx.x;
    g_degF[i] = 0;
    g_degB[i] = 0;
}
__global__ void count_deg_kernel(const int* __restrict__ row, const int* __restrict__ col) {
    int e = blockIdx.x * blockDim.x + threadIdx.x;
    atomicAdd(&g_degF[row[e]], 1);
    atomicAdd(&g_degB[col[e]], 1);
}
__global__ void scan1_kernel() {
    __shared__ int s[1024];
    int b = blockIdx.x;
    const int* deg = (b < 128) ? g_degF : g_degB;
    int* rp = (b < 128) ? g_rpF : g_rpB;
    int base = (b & 127) * 1024;
    for (int i = threadIdx.x; i < 1024; i += blockDim.x) s[i] = deg[base + i];
    __syncthreads();
    if (threadIdx.x == 0) {
        int run = 0;
        for (int i = 0; i < 1024; i++) { int v = s[i]; s[i] = run; run += v; }
        g_bsum[b] = run;
    }
    __syncthreads();
    for (int i = threadIdx.x; i < 1024; i += blockDim.x) rp[base + i] = s[i];
}
__global__ void scan2_kernel() {
    int t = threadIdx.x;
    int base = t * 128;
    int run = 0;
    for (int i = 0; i < 128; i++) { int v = g_bsum[base + i]; g_bsum[base + i] = run; run += v; }
}
__global__ void scan3_kernel() {
    int i = blockIdx.x * blockDim.x + threadIdx.x;
    if (i < NN) {
        int v = g_rpF[i] + g_bsum[i >> 10];
        g_rpF[i] = v; g_fillF[i] = v;
    } else {
        int j = i - NN;
        int v = g_rpB[j] + g_bsum[128 + (j >> 10)];
        g_rpB[j] = v; g_fillB[j] = v;
    }
}
__global__ void fill_csr_kernel(const int* __restrict__ row, const int* __restrict__ col) {
    int e = blockIdx.x * blockDim.x + threadIdx.x;
    int r = row[e], c = col[e];
    int pF = atomicAdd(&g_fillF[r], 1);
    g_eF[pF] = c;
    int pB = atomicAdd(&g_fillB[c], 1);
    g_eB[pB] = r;
}

// ---------------- gather: msg[n] = sum_{e in csr[n]} fm[eidx[e]] ----------------
__global__ void gather_kernel(const int* __restrict__ rp, const int* __restrict__ deg,
                              const int* __restrict__ eidx) {
    int node = (blockIdx.x * blockDim.x + threadIdx.x) >> 5;
    int lane = threadIdx.x & 31;
    if (lane >= 25) return;
    int s0 = rp[node];
    int cnt = deg[node];
    float4 acc = make_float4(0.f, 0.f, 0.f, 0.f);
    for (int i = 0; i < cnt; i++) {
        int s = eidx[s0 + i];
        float4 v = *(const float4*)&g_fm[s * DD + 4 * lane];
        acc.x += v.x; acc.y += v.y; acc.z += v.z; acc.w += v.w;
    }
    *(float4*)&g_msg[node * DD + 4 * lane] = acc;
}

// ---------------- fused 2-layer message MLP (unchanged, FFMA2 path) ----------------
#define MLP_THREADS 256
#define MLP_NODES 64
#define HID 52
#define MLP_SMEM_FLOATS (5000 + HID*DD + MLP_NODES*DD + MLP_NODES*HID + DD + 64)

__global__ void __launch_bounds__(MLP_THREADS, 2)
mlp_kernel(const float* __restrict__ W1, const float* __restrict__ b1,
           const float* __restrict__ W2, const float* __restrict__ b2) {
    extern __shared__ float smem[];
    float* s_w1 = smem;
    float* s_w2 = s_w1 + 5000;
    float* s_h  = s_w2 + HID * DD;
    float* s_hid = s_h + MLP_NODES * DD;
    float* s_b2 = s_hid + MLP_NODES * HID;
    float* s_b1 = s_b2 + DD;

    int tid = threadIdx.x;
    int base = blockIdx.x * MLP_NODES;

    for (int i = tid; i < 5000; i += MLP_THREADS) s_w1[i] = W1[i];
    for (int i = tid; i < HID * DD; i += MLP_THREADS) s_w2[i] = (i < 5000) ? W2[i] : 0.f;
    for (int i = tid; i < MLP_NODES * DD / 4; i += MLP_THREADS)
        ((float4*)s_h)[i] = ((const float4*)g_h)[base * (DD / 4) + i];
    if (tid < DD) s_b2[tid] = b2[tid];
    if (tid < DA) s_b1[tid] = b1[tid];
    __syncthreads();

    int warp = tid >> 5, lane = tid & 31;
    int nb = warp * 8;
    int k0 = 4 * lane;
    bool act = lane < 25;

    if (act) {
        int j0 = 2 * lane;
        u64 bias = pk2(s_b1[j0], s_b1[j0 + 1]);
        u64 acc[8];
#pragma unroll
        for (int nn = 0; nn < 8; nn++) acc[nn] = bias;
        const float* xp = s_h + nb * DD;
#pragma unroll 1
        for (int d4 = 0; d4 < DD; d4 += 4) {
            float4 xv[8];
#pragma unroll
            for (int nn = 0; nn < 8; nn++) xv[nn] = *(const float4*)&xp[nn * DD + d4];
#pragma unroll
            for (int dd = 0; dd < 4; dd++) {
                u64 w = *(const u64*)&s_w1[(d4 + dd) * DA + j0];
#pragma unroll
                for (int nn = 0; nn < 8; nn++)
                    acc[nn] = ffma2(w, dup2(((const float*)&xv[nn])[dd]), acc[nn]);
            }
        }
#pragma unroll
        for (int nn = 0; nn < 8; nn++) {
            float2 v = unpk(acc[nn]);
            *(float2*)&s_hid[(nb + nn) * HID + j0] =
                make_float2(fmaxf(v.x, 0.f), fmaxf(v.y, 0.f));
        }
    } else if (lane == 25) {
#pragma unroll
        for (int nn = 0; nn < 8; nn++)
            *(float2*)&s_hid[(nb + nn) * HID + 50] = make_float2(0.f, 0.f);
    }
    __syncwarp();

    if (act) {
        float4 bb = *(const float4*)&s_b2[k0];
        u64 a[8][2];
#pragma unroll
        for (int nn = 0; nn < 8; nn++) { a[nn][0] = pk2(bb.x, bb.y); a[nn][1] = pk2(bb.z, bb.w); }
        const float* hp = s_hid + nb * HID;
#pragma unroll 1
        for (int j4 = 0; j4 < HID; j4 += 4) {
            float4 hv[8];
#pragma unroll
            for (int nn = 0; nn < 8; nn++) hv[nn] = *(const float4*)&hp[nn * HID + j4];
#pragma unroll
            for (int dd = 0; dd < 4; dd++) {
                ulonglong2 w = *(const ulonglong2*)&s_w2[(j4 + dd) * DD + k0];
#pragma unroll
                for (int nn = 0; nn < 8; nn++) {
                    u64 v = dup2(((const float*)&hv[nn])[dd]);
                    a[nn][0] = ffma2(w.x, v, a[nn][0]);
                    a[nn][1] = ffma2(w.y, v, a[nn][1]);
                }
            }
        }
#pragma unroll
        for (int nn = 0; nn < 8; nn++) {
            float2 p0 = unpk(a[nn][0]), p1 = unpk(a[nn][1]);
            *(float4*)&g_fm[(base + nb + nn) * DD + k0] =
                make_float4(p0.x, p0.y, p1.x, p1.y);
        }
    }
}

// ---------------- mma.sync GRU ----------------
// CTA = 128 nodes, 8 warps (M-strip 16 each), N = 104 (13 n8 tiles), K = 304 (19 k16).
// A tiles (split-bf16): A_msg, A_h in smem [128][312] bf16 (stride 624 B).
// B gate image staged per pass into one smem slot [104][312] bf16.
#define GRU_THREADS 256
#define SA_MSG 0
#define SA_H   79872
#define SB     159744
#define SBI    224640                     // bih, 304 floats
#define SBH    (SBI + 1216)               // bhh, 304 floats
#define GRU_SMEM_BYTES (SBH + 1216)       // 227,072

__device__ __forceinline__ void build_a(unsigned* sa, const float* __restrict__ src, int tid) {
    // sa[row*156 + kp]: K layout [hi(0..99), hi(0..99), lo(0..99), 0 x12]
    for (int idx = tid; idx < 128 * 156; idx += GRU_THREADS) {
        int row = idx / 156;
        int kp = idx - row * 156;
        int k = kp * 2;
        unsigned out = 0;
        if (k < 300) {
            int seg = k / 100;
            int d0 = k - seg * 100;
            float x0 = src[row * DD + d0];
            float x1 = src[row * DD + d0 + 1];
            __nv_bfloat16 h0 = __float2bfloat16(x0), h1 = __float2bfloat16(x1);
            unsigned short u0, u1;
            if (seg == 2) {
                __nv_bfloat16 l0 = __float2bfloat16(x0 - __bfloat162float(h0));
                __nv_bfloat16 l1 = __float2bfloat16(x1 - __bfloat162float(h1));
                u0 = *(unsigned short*)&l0; u1 = *(unsigned short*)&l1;
            } else {
                u0 = *(unsigned short*)&h0; u1 = *(unsigned short*)&h1;
            }
            out = (unsigned)u0 | ((unsigned)u1 << 16);
        }
        sa[row * 156 + kp] = out;
    }
}

__device__ __forceinline__ void gemm_pass(uint32_t aAddr, uint32_t bX4, uint32_t bX2,
                                          float (*acc)[4]) {
#pragma unroll 1
    for (int ks = 0; ks < 19; ks++) {
        uint32_t a0, a1, a2, a3;
        LDSM4(a0, a1, a2, a3, aAddr + ks * 32);
#pragma unroll
        for (int p = 0; p < 6; p++) {
            uint32_t b0, b1, b2, b3;
            LDSM4(b0, b1, b2, b3, bX4 + p * 9984 + ks * 32);
            MMA16816(acc[2 * p],     a0, a1, a2, a3, b0, b1);
            MMA16816(acc[2 * p + 1], a0, a1, a2, a3, b2, b3);
        }
        uint32_t b0, b1;
        LDSM2(b0, b1, bX2 + ks * 32);
        MMA16816(acc[12], a0, a1, a2, a3, b0, b1);
    }
}

__global__ void __launch_bounds__(GRU_THREADS, 1)
gru_mma_kernel(const unsigned char* __restrict__ Bimg,   // 6 images for this direction
               const float* __restrict__ bih, const float* __restrict__ bhh) {
    extern __shared__ unsigned char sm[];
    uint32_t sbase = smem_u32(sm);
    int tid = threadIdx.x, wid = tid >> 5, lane = tid & 31;
    int base = blockIdx.x * 128;
    int lrow = lane & 7, grp = lane >> 3;
    int m0 = wid * 16;

    // ldmatrix lane addresses
    uint32_t aMsg = sbase + SA_MSG + (uint32_t)(m0 + lrow + (grp & 1) * 8) * 624 + (grp >> 1) * 16;
    uint32_t aH   = sbase + SA_H   + (uint32_t)(m0 + lrow + (grp & 1) * 8) * 624 + (grp >> 1) * 16;
    uint32_t bX4  = sbase + SB + (uint32_t)(lrow + (grp >> 1) * 8) * 624 + (grp & 1) * 16;
    uint32_t bX2  = sbase + SB + (uint32_t)(96 + lrow) * 624 + (grp & 1) * 16;

    // stage A tiles + biases
    build_a((unsigned*)(sm + SA_MSG), g_msg + (size_t)base * DD, tid);
    build_a((unsigned*)(sm + SA_H),   g_h   + (size_t)base * DD, tid);
    {
        float* bi = (float*)(sm + SBI);
        float* bh = (float*)(sm + SBH);
        for (int i = tid; i < 304; i += GRU_THREADS) {
            bi[i] = (i < 300) ? bih[i] : 0.f;
            bh[i] = (i < 300) ? bhh[i] : 0.f;
        }
    }
    const float* s_bi = (const float*)(sm + SBI);
    const float* s_bh = (const float*)(sm + SBH);

    float accA[13][4], accB[13][4];
#pragma unroll
    for (int t = 0; t < 13; t++)
#pragma unroll
        for (int q = 0; q < 4; q++) { accA[t][q] = 0.f; accB[t][q] = 0.f; }

#define STAGE_B(img) do { \
        __syncthreads(); \
        const int4* _s = (const int4*)(Bimg + (size_t)(img) * 64896); \
        int4* _d = (int4*)(sm + SB); \
        for (int i = tid; i < 4056; i += GRU_THREADS) _d[i] = _s[i]; \
        __syncthreads(); \
    } while (0)

    int jc = 2 * (lane & 3);   // col within tile for c0/c1 (c2/c3 same cols, row+8)

    // r gate: accA = A_msg@Wih_r + A_h@Whh_r -> sigmoid
    STAGE_B(0); gemm_pass(aMsg, bX4, bX2, accA);
    STAGE_B(3); gemm_pass(aH,   bX4, bX2, accA);
#pragma unroll
    for (int t = 0; t < 13; t++) {
        int j = t * 8 + jc;
#pragma unroll
        for (int q = 0; q < 4; q++) {
            int jj = j + (q & 1);
            accA[t][q] = sigf(accA[t][q] + s_bi[jj] + s_bh[jj]);
        }
    }
    // gh_n: accB = A_h@Whh_n; accA = r * (gh_n + bhh_n)
    STAGE_B(5); gemm_pass(aH, bX4, bX2, accB);
#pragma unroll
    for (int t = 0; t < 13; t++) {
        int j = t * 8 + jc;
#pragma unroll
        for (int q = 0; q < 4; q++) {
            accA[t][q] *= (accB[t][q] + s_bh[200 + j + (q & 1)]);
            accB[t][q] = 0.f;
        }
    }
    // gi_n: accB = A_msg@Wih_n; accA = nv = tanh(gi_n + bih_n + accA)
    STAGE_B(2); gemm_pass(aMsg, bX4, bX2, accB);
#pragma unroll
    for (int t = 0; t < 13; t++) {
        int j = t * 8 + jc;
#pragma unroll
        for (int q = 0; q < 4; q++) {
            accA[t][q] = tanhf(accB[t][q] + s_bi[200 + j + (q & 1)] + accA[t][q]);
            accB[t][q] = 0.f;
        }
    }
    // z gate: accB = A_msg@Wih_z + A_h@Whh_z -> sigmoid
    STAGE_B(1); gemm_pass(aMsg, bX4, bX2, accB);
    STAGE_B(4); gemm_pass(aH,   bX4, bX2, accB);
#pragma unroll
    for (int t = 0; t < 13; t++) {
        int j = t * 8 + jc;
#pragma unroll
        for (int q = 0; q < 4; q++) {
            int jj = 100 + j + (q & 1);
            accB[t][q] = sigf(accB[t][q] + s_bi[jj] + s_bh[jj]);
        }
    }
    // h' = (1-z)*nv + z*h  (read old h from gmem, write back)
    {
        int r0 = base + m0 + (lane >> 2);
        int r1 = r0 + 8;
#pragma unroll
        for (int t = 0; t < 13; t++) {
            int j = t * 8 + jc;
            if (j < 100) {
                float2 h0 = *(const float2*)&g_h[(size_t)r0 * DD + j];
                float2 h1 = *(const float2*)&g_h[(size_t)r1 * DD + j];
                float2 o0, o1;
                o0.x = (1.f - accB[t][0]) * accA[t][0] + accB[t][0] * h0.x;
                o0.y = (1.f - accB[t][1]) * accA[t][1] + accB[t][1] * h0.y;
                o1.x = (1.f - accB[t][2]) * accA[t][2] + accB[t][2] * h1.x;
                o1.y = (1.f - accB[t][3]) * accA[t][3] + accB[t][3] * h1.y;
                *(float2*)&g_h[(size_t)r0 * DD + j] = o0;
                *(float2*)&g_h[(size_t)r1 * DD + j] = o1;
            }
        }
    }
#undef STAGE_B
}

// ---------------- classifier ----------------
__global__ void cls_kernel(const float* __restrict__ W1, const float* __restrict__ b1,
                           const float* __restrict__ W2, const float* __restrict__ b2,
                           float* __restrict__ out) {
    __shared__ float s_w1[DD * DC];
    __shared__ float s_b1[DC];
    __shared__ float s_w2[DC];
    __shared__ float s_row[8 * DD];

    int tid = threadIdx.x;
    int warp = tid >> 5, lane = tid & 31;
    int node = blockIdx.x * 8 + warp;

    for (int i = tid; i < DD * DC; i += blockDim.x) s_w1[i] = W1[i];
    if (tid < DC) { s_b1[tid] = b1[tid]; s_w2[tid] = W2[tid]; }
    __syncthreads();

    const float* hrow = &g_h[(size_t)node * DD];
    float* rbuf = &s_row[warp * DD];
    rbuf[lane] = hrow[lane];
    rbuf[lane + 32] = hrow[lane + 32];
    rbuf[lane + 64] = hrow[lane + 64];
    if (lane < 4) rbuf[lane + 96] = hrow[lane + 96];
    __syncwarp();

    float v = 0.f;
    if (lane < DC) {
        float acc = s_b1[lane];
#pragma unroll 4
        for (int d = 0; d < DD; d++) acc += rbuf[d] * s_w1[d * DC + lane];
        v = fmaxf(acc, 0.f) * s_w2[lane];
    }
#pragma unroll
    for (int off = 16; off > 0; off >>= 1) v += __shfl_down_sync(0xFFFFFFFFu, v, off);
    if (lane == 0) out[node] = v + b2[0];
}

// ---------------- host launch ----------------
extern "C" void kernel_launch(void* const* d_in, const int* in_sizes, int n_in,
                              void* d_out, int out_size) {
    const float* features = (const float*)d_in[0];
    const int* edge_row   = (const int*)d_in[1];
    const int* edge_col   = (const int*)d_in[2];
    const float* init_W = (const float*)d_in[3];
    const float* init_b = (const float*)d_in[4];
    const float* fmsg_W1 = (const float*)d_in[5];
    const float* fmsg_b1 = (const float*)d_in[6];
    const float* fmsg_W2 = (const float*)d_in[7];
    const float* fmsg_b2 = (const float*)d_in[8];
    const float* bmsg_W1 = (const float*)d_in[9];
    const float* bmsg_b1 = (const float*)d_in[10];
    const float* bmsg_W2 = (const float*)d_in[11];
    const float* bmsg_b2 = (const float*)d_in[12];
    const float* fgru_Wih = (const float*)d_in[13];
    const float* fgru_Whh = (const float*)d_in[14];
    const float* fgru_bih = (const float*)d_in[15];
    const float* fgru_bhh = (const float*)d_in[16];
    const float* bgru_Wih = (const float*)d_in[17];
    const float* bgru_Whh = (const float*)d_in[18];
    const float* bgru_bih = (const float*)d_in[19];
    const float* bgru_bhh = (const float*)d_in[20];
    const float* cls_W1 = (const float*)d_in[21];
    const float* cls_b1 = (const float*)d_in[22];
    const float* cls_W2 = (const float*)d_in[23];
    const float* cls_b2 = (const float*)d_in[24];
    float* out = (float*)d_out;

    const int mlp_smem = MLP_SMEM_FLOATS * 4;
    cudaFuncSetAttribute((const void*)mlp_kernel,
                         cudaFuncAttributeMaxDynamicSharedMemorySize, mlp_smem);
    cudaFuncSetAttribute((const void*)gru_mma_kernel,
                         cudaFuncAttributeMaxDynamicSharedMemorySize, GRU_SMEM_BYTES);

    unsigned char* bimg_base = nullptr;
    cudaGetSymbolAddress((void**)&bimg_base, g_Bimg);
    const unsigned char* BimgF = bimg_base;
    const unsigned char* BimgB = bimg_base + 6 * 64896;

    int *rpF, *rpB, *degF, *degB, *eF, *eB;
    cudaGetSymbolAddress((void**)&rpF, g_rpF);
    cudaGetSymbolAddress((void**)&rpB, g_rpB);
    cudaGetSymbolAddress((void**)&degF, g_degF);
    cudaGetSymbolAddress((void**)&degB, g_degB);
    cudaGetSymbolAddress((void**)&eF, g_eF);
    cudaGetSymbolAddress((void**)&eB, g_eB);

    init_kernel<<<(ND + 255) / 256, 256>>>(features, init_W, init_b);
    prep_b_kernel<<<(12 * 16224 + 255) / 256, 256>>>(fgru_Wih, fgru_Whh, bgru_Wih, bgru_Whh);

    // CSR build (edges constant across rounds)
    zero_deg_kernel<<<NN / 256, 256>>>();
    count_deg_kernel<<<EE / 256, 256>>>(edge_row, edge_col);
    scan1_kernel<<<256, 256>>>();
    scan2_kernel<<<1, 2>>>();
    scan3_kernel<<<(2 * NN) / 256, 256>>>();
    fill_csr_kernel<<<EE / 256, 256>>>(edge_row, edge_col);

    const int mlp_blocks = NN / MLP_NODES;   // 2048
    const int gru_blocks = NN / 128;         // 1024
    const int gat_blocks = NN / 8;           // 16384

    for (int r = 0; r < 20; r++) {
        // forward: msg[row] = sum fm[col]
        mlp_kernel<<<mlp_blocks, MLP_THREADS, mlp_smem>>>(fmsg_W1, fmsg_b1, fmsg_W2, fmsg_b2);
        gather_kernel<<<gat_blocks, 256>>>(rpF, degF, eF);
        gru_mma_kernel<<<gru_blocks, GRU_THREADS, GRU_SMEM_BYTES>>>(BimgF, fgru_bih, fgru_bhh);
        // backward: msg[col] = sum bm[row]
        mlp_kernel<<<mlp_blocks, MLP_THREADS, mlp_smem>>>(bmsg_W1, bmsg_b1, bmsg_W2, bmsg_b2);
        gather_kernel<<<gat_blocks, 256>>>(rpB, degB, eB);
        gru_mma_kernel<<<gru_blocks, GRU_THREADS, GRU_SMEM_BYTES>>>(BimgB, bgru_bih, bgru_bhh);
    }

    cls_kernel<<<NN / 8, 256>>>(cls_W1, cls_b1, cls_W2, cls_b2, out);
    (void)in_sizes; (void)n_in; (void)out_size;
}

// round 8
// speedup vs baseline: 1.4707x; 1.4707x over previous
#include <cuda_runtime.h>
#include <cuda_bf16.h>
#include <cstdint>

// ---------------- problem constants ----------------
#define NN 131072
#define EE 524288
#define DD 100
#define TD 300
#define DA 50
#define DC 30
#define ND (NN*DD)          // 13,107,200

// ---------------- scratch (static device globals; no allocation) ----------------
__device__ float g_h[ND];
__device__ float g_fm[ND];
__device__ float g_msg[ND];
__device__ float g_WT[4][30000];   // pre-transposed [d][j] GRU weights: fWih,fWhh,bWih,bWhh

// CSR scratch (edges constant -> build once per launch)
__device__ int g_degF[NN], g_degB[NN];
__device__ int g_rpF[NN], g_rpB[NN];
__device__ int g_fillF[NN], g_fillB[NN];
__device__ int g_eF[EE], g_eB[EE];
__device__ int g_bsum[256];

// ---------------- f32x2 packed-FMA helpers (sm_103a FFMA2 path) ----------------
typedef unsigned long long u64;

__device__ __forceinline__ u64 ffma2(u64 a, u64 b, u64 c) {
    u64 d;
    asm("fma.rn.f32x2 %0, %1, %2, %3;" : "=l"(d) : "l"(a), "l"(b), "l"(c));
    return d;
}
__device__ __forceinline__ u64 dup2(float x) {
    u64 d;
    asm("mov.b64 %0, {%1, %1};" : "=l"(d) : "f"(x));
    return d;
}
__device__ __forceinline__ u64 pk2(float a, float b) {
    u64 d;
    asm("mov.b64 %0, {%1, %2};" : "=l"(d) : "f"(a), "f"(b));
    return d;
}
__device__ __forceinline__ float2 unpk(u64 a) {
    float2 r;
    asm("mov.b64 {%0, %1}, %2;" : "=f"(r.x), "=f"(r.y) : "l"(a));
    return r;
}
__device__ __forceinline__ float sigf(float v) {
    return 1.0f / (1.0f + __expf(-v));
}

// ---------------- init: h = features @ init_W + init_b ----------------
__global__ void init_kernel(const float* __restrict__ feat,
                            const float* __restrict__ W,
                            const float* __restrict__ b) {
    int i = blockIdx.x * blockDim.x + threadIdx.x;
    if (i >= ND) return;
    int n = i / DD;
    int d = i - n * DD;
    float f0 = feat[n * 4 + 0], f1 = feat[n * 4 + 1];
    float f2 = feat[n * 4 + 2], f3 = feat[n * 4 + 3];
    g_h[i] = b[d] + f0 * W[d] + f1 * W[DD + d] + f2 * W[2 * DD + d] + f3 * W[3 * DD + d];
}

// ---------------- one-time weight transpose: g_WT[m][d*300+j] = W[j*100+d] ----------------
__global__ void transpose_w_kernel(const float* __restrict__ A, const float* __restrict__ B,
                                   const float* __restrict__ C, const float* __restrict__ E) {
    int i = blockIdx.x * blockDim.x + threadIdx.x;
    if (i >= 30000) return;
    int d = i / TD, j = i - d * TD;
    int src = j * DD + d;
    g_WT[0][i] = A[src];
    g_WT[1][i] = B[src];
    g_WT[2][i] = C[src];
    g_WT[3][i] = E[src];
}

// ---------------- CSR build kernels ----------------
__global__ void zero_deg_kernel() {
    int i = blockIdx.x * blockDim.x + threadIdx.x;
    g_degF[i] = 0;
    g_degB[i] = 0;
}
__global__ void count_deg_kernel(const int* __restrict__ row, const int* __restrict__ col) {
    int e = blockIdx.x * blockDim.x + threadIdx.x;
    atomicAdd(&g_degF[row[e]], 1);
    atomicAdd(&g_degB[col[e]], 1);
}
__global__ void scan1_kernel() {   // grid 256: blocks 0..127 -> F, 128..255 -> B
    __shared__ int s[1024];
    int b = blockIdx.x;
    const int* deg = (b < 128) ? g_degF : g_degB;
    int* rp = (b < 128) ? g_rpF : g_rpB;
    int base = (b & 127) * 1024;
    for (int i = threadIdx.x; i < 1024; i += blockDim.x) s[i] = deg[base + i];
    __syncthreads();
    if (threadIdx.x == 0) {
        int run = 0;
        for (int i = 0; i < 1024; i++) { int v = s[i]; s[i] = run; run += v; }
        g_bsum[b] = run;
    }
    __syncthreads();
    for (int i = threadIdx.x; i < 1024; i += blockDim.x) rp[base + i] = s[i];
}
__global__ void scan2_kernel() {
    int t = threadIdx.x;
    int base = t * 128;
    int run = 0;
    for (int i = 0; i < 128; i++) { int v = g_bsum[base + i]; g_bsum[base + i] = run; run += v; }
}
__global__ void scan3_kernel() {
    int i = blockIdx.x * blockDim.x + threadIdx.x;
    if (i < NN) {
        int v = g_rpF[i] + g_bsum[i >> 10];
        g_rpF[i] = v; g_fillF[i] = v;
    } else {
        int j = i - NN;
        int v = g_rpB[j] + g_bsum[128 + (j >> 10)];
        g_rpB[j] = v; g_fillB[j] = v;
    }
}
__global__ void fill_csr_kernel(const int* __restrict__ row, const int* __restrict__ col) {
    int e = blockIdx.x * blockDim.x + threadIdx.x;
    int r = row[e], c = col[e];
    int pF = atomicAdd(&g_fillF[r], 1);
    g_eF[pF] = c;
    int pB = atomicAdd(&g_fillB[c], 1);
    g_eB[pB] = r;
}

// ---------------- gather: msg[n] = sum_{e in csr[n]} fm[eidx[e]] ----------------
__global__ void gather_kernel(const int* __restrict__ rp, const int* __restrict__ deg,
                              const int* __restrict__ eidx) {
    int node = (blockIdx.x * blockDim.x + threadIdx.x) >> 5;
    int lane = threadIdx.x & 31;
    if (lane >= 25) return;
    int s0 = rp[node];
    int cnt = deg[node];
    float4 acc = make_float4(0.f, 0.f, 0.f, 0.f);
    for (int i = 0; i < cnt; i++) {
        int s = eidx[s0 + i];
        float4 v = *(const float4*)&g_fm[s * DD + 4 * lane];
        acc.x += v.x; acc.y += v.y; acc.z += v.z; acc.w += v.w;
    }
    *(float4*)&g_msg[node * DD + 4 * lane] = acc;
}

// ---------------- fused 2-layer message MLP (8 nodes/warp, float4 x bcast) ----------------
#define MLP_THREADS 256
#define MLP_NODES 64
#define HID 52
#define MLP_SMEM_FLOATS (5000 + HID*DD + MLP_NODES*DD + MLP_NODES*HID + DD + 64)

__global__ void __launch_bounds__(MLP_THREADS, 2)
mlp_kernel(const float* __restrict__ W1, const float* __restrict__ b1,
           const float* __restrict__ W2, const float* __restrict__ b2) {
    extern __shared__ float smem[];
    float* s_w1 = smem;
    float* s_w2 = s_w1 + 5000;
    float* s_h  = s_w2 + HID * DD;
    float* s_hid = s_h + MLP_NODES * DD;
    float* s_b2 = s_hid + MLP_NODES * HID;
    float* s_b1 = s_b2 + DD;

    int tid = threadIdx.x;
    int base = blockIdx.x * MLP_NODES;

    for (int i = tid; i < 5000; i += MLP_THREADS) s_w1[i] = W1[i];
    for (int i = tid; i < HID * DD; i += MLP_THREADS) s_w2[i] = (i < 5000) ? W2[i] : 0.f;
    for (int i = tid; i < MLP_NODES * DD / 4; i += MLP_THREADS)
        ((float4*)s_h)[i] = ((const float4*)g_h)[base * (DD / 4) + i];
    if (tid < DD) s_b2[tid] = b2[tid];
    if (tid < DA) s_b1[tid] = b1[tid];
    __syncthreads();

    int warp = tid >> 5, lane = tid & 31;
    int nb = warp * 8;
    int k0 = 4 * lane;
    bool act = lane < 25;

    if (act) {
        int j0 = 2 * lane;
        u64 bias = pk2(s_b1[j0], s_b1[j0 + 1]);
        u64 acc[8];
#pragma unroll
        for (int nn = 0; nn < 8; nn++) acc[nn] = bias;
        const float* xp = s_h + nb * DD;
#pragma unroll 1
        for (int d4 = 0; d4 < DD; d4 += 4) {
            float4 xv[8];
#pragma unroll
            for (int nn = 0; nn < 8; nn++) xv[nn] = *(const float4*)&xp[nn * DD + d4];
#pragma unroll
            for (int dd = 0; dd < 4; dd++) {
                u64 w = *(const u64*)&s_w1[(d4 + dd) * DA + j0];
#pragma unroll
                for (int nn = 0; nn < 8; nn++)
                    acc[nn] = ffma2(w, dup2(((const float*)&xv[nn])[dd]), acc[nn]);
            }
        }
#pragma unroll
        for (int nn = 0; nn < 8; nn++) {
            float2 v = unpk(acc[nn]);
            *(float2*)&s_hid[(nb + nn) * HID + j0] =
                make_float2(fmaxf(v.x, 0.f), fmaxf(v.y, 0.f));
        }
    } else if (lane == 25) {
#pragma unroll
        for (int nn = 0; nn < 8; nn++)
            *(float2*)&s_hid[(nb + nn) * HID + 50] = make_float2(0.f, 0.f);
    }
    __syncwarp();

    if (act) {
        float4 bb = *(const float4*)&s_b2[k0];
        u64 a[8][2];
#pragma unroll
        for (int nn = 0; nn < 8; nn++) { a[nn][0] = pk2(bb.x, bb.y); a[nn][1] = pk2(bb.z, bb.w); }
        const float* hp = s_hid + nb * HID;
#pragma unroll 1
        for (int j4 = 0; j4 < HID; j4 += 4) {
            float4 hv[8];
#pragma unroll
            for (int nn = 0; nn < 8; nn++) hv[nn] = *(const float4*)&hp[nn * HID + j4];
#pragma unroll
            for (int dd = 0; dd < 4; dd++) {
                ulonglong2 w = *(const ulonglong2*)&s_w2[(j4 + dd) * DD + k0];
#pragma unroll
                for (int nn = 0; nn < 8; nn++) {
                    u64 v = dup2(((const float*)&hv[nn])[dd]);
                    a[nn][0] = ffma2(w.x, v, a[nn][0]);
                    a[nn][1] = ffma2(w.y, v, a[nn][1]);
                }
            }
        }
#pragma unroll
        for (int nn = 0; nn < 8; nn++) {
            float2 p0 = unpk(a[nn][0]), p1 = unpk(a[nn][1]);
            *(float4*)&g_fm[(base + nb + nn) * DD + k0] =
                make_float4(p0.x, p0.y, p1.x, p1.y);
        }
    }
}

// ---------------- 6-pass GRU: 2 CTAs/SM, gate partials live in registers ----------------
// CTA = 64 nodes, 256 threads, 8 nodes/warp. smem: one 100x100 gate matrix (40KB),
// msg tile, h tile, biases -> 93.6KB => 2 CTAs/SM (16 warps/SM).
#define GRU_THREADS 256
#define GRU_NODES 64
#define GRU_SMEM_FLOATS 23408
// s_w[0,10000) s_xm[10000,16400) s_xh[16400,22800) s_bi[22800,23104) s_bh[23104,23408)

__global__ void __launch_bounds__(GRU_THREADS, 2)
gru_kernel(const float* __restrict__ WTih, const float* __restrict__ WThh,
           const float* __restrict__ bih, const float* __restrict__ bhh) {
    extern __shared__ float sm[];
    float* s_w  = sm;
    float* s_xm = sm + 10000;
    float* s_xh = sm + 16400;
    float* s_bi = sm + 22800;
    float* s_bh = sm + 23104;

    int tid = threadIdx.x;
    int base = blockIdx.x * GRU_NODES;
    int warp = tid >> 5, lane = tid & 31;
    int nb = warp * 8;
    int k0 = 4 * lane;
    bool act = lane < 25;

    // stage node tiles + biases (s_w staged by STAGE_W below)
    for (int i = tid; i < GRU_NODES * DD / 4; i += GRU_THREADS) {
        ((float4*)s_xm)[i] = ((const float4*)g_msg)[base * (DD / 4) + i];
        ((float4*)s_xh)[i] = ((const float4*)g_h)[base * (DD / 4) + i];
    }
    for (int i = tid; i < TD; i += GRU_THREADS) { s_bi[i] = bih[i]; s_bh[i] = bhh[i]; }

    // stage one transposed gate matrix [d][100] from g_WT ([d][300] layout), OFS4 in float4s
#define STAGE_W(SRC, OFS4) do { \
        __syncthreads(); \
        for (int i = tid; i < 2500; i += GRU_THREADS) { \
            int d = i / 25, q = i - d * 25; \
            ((float4*)s_w)[i] = ((const float4*)(SRC))[d * 75 + (OFS4) + q]; \
        } \
        __syncthreads(); \
    } while (0)

    u64 acc[8][2];
    float rg[8][4];

    // matvec: acc += s_x @ s_w  (100 in-dims, 100 out-cols; lane owns cols k0..k0+3)
#define MATVEC(SX) do { \
        const float* xp_ = (SX) + nb * DD; \
        _Pragma("unroll 1") \
        for (int d4 = 0; d4 < DD; d4 += 4) { \
            float4 xv[8]; \
            _Pragma("unroll") \
            for (int nn = 0; nn < 8; nn++) xv[nn] = *(const float4*)&xp_[nn * DD + d4]; \
            _Pragma("unroll") \
            for (int dd = 0; dd < 4; dd++) { \
                ulonglong2 w = *(const ulonglong2*)&s_w[(d4 + dd) * DD + k0]; \
                _Pragma("unroll") \
                for (int nn = 0; nn < 8; nn++) { \
                    u64 v = dup2(((const float*)&xv[nn])[dd]); \
                    acc[nn][0] = ffma2(w.x, v, acc[nn][0]); \
                    acc[nn][1] = ffma2(w.y, v, acc[nn][1]); \
                } \
            } \
        } \
    } while (0)

#define ZERO_ACC() do { \
        _Pragma("unroll") \
        for (int nn = 0; nn < 8; nn++) { acc[nn][0] = 0ULL; acc[nn][1] = 0ULL; } \
    } while (0)

    // ---- r gate: r = sig(msg@Wr_ih + h@Wr_hh + bi_r + bh_r) ----
    STAGE_W(WTih, 0);
    if (act) { ZERO_ACC(); MATVEC(s_xm); }
    STAGE_W(WThh, 0);
    if (act) {
        MATVEC(s_xh);
        float4 b1v = *(const float4*)&s_bi[k0];
        float4 b2v = *(const float4*)&s_bh[k0];
#pragma unroll
        for (int nn = 0; nn < 8; nn++) {
            float2 a0 = unpk(acc[nn][0]), a1 = unpk(acc[nn][1]);
            rg[nn][0] = sigf(a0.x + b1v.x + b2v.x);
            rg[nn][1] = sigf(a0.y + b1v.y + b2v.y);
            rg[nn][2] = sigf(a1.x + b1v.z + b2v.z);
            rg[nn][3] = sigf(a1.y + b1v.w + b2v.w);
        }
    }
    // ---- n gate: nv = tanh(msg@Wn_ih + bi_n + r*(h@Wn_hh + bh_n)) ----
    STAGE_W(WThh, 50);
    if (act) {
        ZERO_ACC(); MATVEC(s_xh);
        float4 bn = *(const float4*)&s_bh[200 + k0];
#pragma unroll
        for (int nn = 0; nn < 8; nn++) {
            float2 a0 = unpk(acc[nn][0]), a1 = unpk(acc[nn][1]);
            acc[nn][0] = pk2(rg[nn][0] * (a0.x + bn.x), rg[nn][1] * (a0.y + bn.y));
            acc[nn][1] = pk2(rg[nn][2] * (a1.x + bn.z), rg[nn][3] * (a1.y + bn.w));
        }
    }
    STAGE_W(WTih, 50);
    if (act) {
        MATVEC(s_xm);
        float4 bn = *(const float4*)&s_bi[200 + k0];
#pragma unroll
        for (int nn = 0; nn < 8; nn++) {
            float2 a0 = unpk(acc[nn][0]), a1 = unpk(acc[nn][1]);
            rg[nn][0] = tanhf(a0.x + bn.x);
            rg[nn][1] = tanhf(a0.y + bn.y);
            rg[nn][2] = tanhf(a1.x + bn.z);
            rg[nn][3] = tanhf(a1.y + bn.w);
        }
    }
    // ---- z gate + state update ----
    STAGE_W(WTih, 25);
    if (act) { ZERO_ACC(); MATVEC(s_xm); }
    STAGE_W(WThh, 25);
    if (act) {
        MATVEC(s_xh);
        float4 b1v = *(const float4*)&s_bi[100 + k0];
        float4 b2v = *(const float4*)&s_bh[100 + k0];
#pragma unroll
        for (int nn = 0; nn < 8; nn++) {
            float2 a0 = unpk(acc[nn][0]), a1 = unpk(acc[nn][1]);
            float z0 = sigf(a0.x + b1v.x + b2v.x);
            float z1 = sigf(a0.y + b1v.y + b2v.y);
            float z2 = sigf(a1.x + b1v.z + b2v.z);
            float z3 = sigf(a1.y + b1v.w + b2v.w);
            float4 hv = *(const float4*)&s_xh[(nb + nn) * DD + k0];
            float4 o;
            o.x = (1.f - z0) * rg[nn][0] + z0 * hv.x;
            o.y = (1.f - z1) * rg[nn][1] + z1 * hv.y;
            o.z = (1.f - z2) * rg[nn][2] + z2 * hv.z;
            o.w = (1.f - z3) * rg[nn][3] + z3 * hv.w;
            *(float4*)&g_h[(size_t)(base + nb + nn) * DD + k0] = o;
        }
    }
#undef STAGE_W
#undef MATVEC
#undef ZERO_ACC
}

// ---------------- classifier ----------------
__global__ void cls_kernel(const float* __restrict__ W1, const float* __restrict__ b1,
                           const float* __restrict__ W2, const float* __restrict__ b2,
                           float* __restrict__ out) {
    __shared__ float s_w1[DD * DC];
    __shared__ float s_b1[DC];
    __shared__ float s_w2[DC];
    __shared__ float s_row[8 * DD];

    int tid = threadIdx.x;
    int warp = tid >> 5, lane = tid & 31;
    int node = blockIdx.x * 8 + warp;

    for (int i = tid; i < DD * DC; i += blockDim.x) s_w1[i] = W1[i];
    if (tid < DC) { s_b1[tid] = b1[tid]; s_w2[tid] = W2[tid]; }
    __syncthreads();

    const float* hrow = &g_h[(size_t)node * DD];
    float* rbuf = &s_row[warp * DD];
    rbuf[lane] = hrow[lane];
    rbuf[lane + 32] = hrow[lane + 32];
    rbuf[lane + 64] = hrow[lane + 64];
    if (lane < 4) rbuf[lane + 96] = hrow[lane + 96];
    __syncwarp();

    float v = 0.f;
    if (lane < DC) {
        float acc = s_b1[lane];
#pragma unroll 4
        for (int d = 0; d < DD; d++) acc += rbuf[d] * s_w1[d * DC + lane];
        v = fmaxf(acc, 0.f) * s_w2[lane];
    }
#pragma unroll
    for (int off = 16; off > 0; off >>= 1) v += __shfl_down_sync(0xFFFFFFFFu, v, off);
    if (lane == 0) out[node] = v + b2[0];
}

// ---------------- host launch ----------------
extern "C" void kernel_launch(void* const* d_in, const int* in_sizes, int n_in,
                              void* d_out, int out_size) {
    const float* features = (const float*)d_in[0];
    const int* edge_row   = (const int*)d_in[1];
    const int* edge_col   = (const int*)d_in[2];
    const float* init_W = (const float*)d_in[3];
    const float* init_b = (const float*)d_in[4];
    const float* fmsg_W1 = (const float*)d_in[5];
    const float* fmsg_b1 = (const float*)d_in[6];
    const float* fmsg_W2 = (const float*)d_in[7];
    const float* fmsg_b2 = (const float*)d_in[8];
    const float* bmsg_W1 = (const float*)d_in[9];
    const float* bmsg_b1 = (const float*)d_in[10];
    const float* bmsg_W2 = (const float*)d_in[11];
    const float* bmsg_b2 = (const float*)d_in[12];
    const float* fgru_Wih = (const float*)d_in[13];
    const float* fgru_Whh = (const float*)d_in[14];
    const float* fgru_bih = (const float*)d_in[15];
    const float* fgru_bhh = (const float*)d_in[16];
    const float* bgru_Wih = (const float*)d_in[17];
    const float* bgru_Whh = (const float*)d_in[18];
    const float* bgru_bih = (const float*)d_in[19];
    const float* bgru_bhh = (const float*)d_in[20];
    const float* cls_W1 = (const float*)d_in[21];
    const float* cls_b1 = (const float*)d_in[22];
    const float* cls_W2 = (const float*)d_in[23];
    const float* cls_b2 = (const float*)d_in[24];
    float* out = (float*)d_out;

    const int mlp_smem = MLP_SMEM_FLOATS * 4;
    const int gru_smem = GRU_SMEM_FLOATS * 4;   // 93,632 B
    cudaFuncSetAttribute((const void*)mlp_kernel,
                         cudaFuncAttributeMaxDynamicSharedMemorySize, mlp_smem);
    cudaFuncSetAttribute((const void*)gru_kernel,
                         cudaFuncAttributeMaxDynamicSharedMemorySize, gru_smem);

    // resolve device-global scratch addresses
    float* wt_base = nullptr;
    cudaGetSymbolAddress((void**)&wt_base, g_WT);
    const float* fWihT = wt_base;
    const float* fWhhT = wt_base + 30000;
    const float* bWihT = wt_base + 60000;
    const float* bWhhT = wt_base + 90000;
    int *rpF, *rpB, *degF, *degB, *eF, *eB;
    cudaGetSymbolAddress((void**)&rpF, g_rpF);
    cudaGetSymbolAddress((void**)&rpB, g_rpB);
    cudaGetSymbolAddress((void**)&degF, g_degF);
    cudaGetSymbolAddress((void**)&degB, g_degB);
    cudaGetSymbolAddress((void**)&eF, g_eF);
    cudaGetSymbolAddress((void**)&eB, g_eB);

    init_kernel<<<(ND + 255) / 256, 256>>>(features, init_W, init_b);
    transpose_w_kernel<<<(30000 + 255) / 256, 256>>>(fgru_Wih, fgru_Whh, bgru_Wih, bgru_Whh);

    // CSR build (edges constant across rounds)
    zero_deg_kernel<<<NN / 256, 256>>>();
    count_deg_kernel<<<EE / 256, 256>>>(edge_row, edge_col);
    scan1_kernel<<<256, 256>>>();
    scan2_kernel<<<1, 2>>>();
    scan3_kernel<<<(2 * NN) / 256, 256>>>();
    fill_csr_kernel<<<EE / 256, 256>>>(edge_row, edge_col);

    const int mlp_blocks = NN / MLP_NODES;   // 2048
    const int gru_blocks = NN / GRU_NODES;   // 2048
    const int gat_blocks = NN / 8;           // 16384

    for (int r = 0; r < 20; r++) {
        // forward: msg[row] = sum fm[col]
        mlp_kernel<<<mlp_blocks, MLP_THREADS, mlp_smem>>>(fmsg_W1, fmsg_b1, fmsg_W2, fmsg_b2);
        gather_kernel<<<gat_blocks, 256>>>(rpF, degF, eF);
        gru_kernel<<<gru_blocks, GRU_THREADS, gru_smem>>>(fWihT, fWhhT, fgru_bih, fgru_bhh);
        // backward: msg[col] = sum bm[row]
        mlp_kernel<<<mlp_blocks, MLP_THREADS, mlp_smem>>>(bmsg_W1, bmsg_b1, bmsg_W2, bmsg_b2);
        gather_kernel<<<gat_blocks, 256>>>(rpB, degB, eB);
        gru_kernel<<<gru_blocks, GRU_THREADS, gru_smem>>>(bWihT, bWhhT, bgru_bih, bgru_bhh);
    }

    cls_kernel<<<NN / 8, 256>>>(cls_W1, cls_b1, cls_W2, cls_b2, out);
    (void)in_sizes; (void)n_in; (void)out_size;
}